// round 8
// baseline (speedup 1.0000x reference)
#include <cuda_runtime.h>
#include <cuda_fp16.h>
#include <math.h>
#include <stdint.h>

#define S_LEN   8192
#define BATCH   4
#define DMODEL  1024
#define NROWS   (BATCH * S_LEN)   // 32768
#define NHEADS  16
#define DHEAD   64

// Scratch (device globals: allocation-free per harness rules)
__device__ float  g_k[(size_t)NROWS * DMODEL];    // fp32 K features
__device__ float  g_v[(size_t)NROWS * DMODEL];    // fp32 V
__device__ __half g_fq[(size_t)NROWS * DMODEL];   // fp16 Q features
__device__ __half g_hq[(size_t)NROWS * DMODEL];   // fp16-rounded inputs
__device__ __half g_hk[(size_t)NROWS * DMODEL];
__device__ __half g_hv[(size_t)NROWS * DMODEL];
__device__ __half g_hattn[(size_t)NROWS * DMODEL];
__device__ __half g_hw[4][DMODEL * DMODEL];       // fp16-rounded weights
__device__ float  g_kv[BATCH * NHEADS * DHEAD * DHEAD];   // [b,h,dv,dk]
__device__ __half g_kvh[BATCH * NHEADS * DHEAD * DHEAD];
__device__ float  g_ksum[BATCH * NHEADS * DHEAD];

// ---------------------------------------------------------------------------
// helpers
// ---------------------------------------------------------------------------
__device__ __forceinline__ void mma_fp16(float* c, const unsigned* a, const unsigned* b) {
    asm volatile(
        "mma.sync.aligned.m16n8k16.row.col.f32.f16.f16.f32 "
        "{%0,%1,%2,%3}, {%4,%5,%6,%7}, {%8,%9}, {%0,%1,%2,%3};"
        : "+f"(c[0]), "+f"(c[1]), "+f"(c[2]), "+f"(c[3])
        : "r"(a[0]), "r"(a[1]), "r"(a[2]), "r"(a[3]), "r"(b[0]), "r"(b[1]));
}

__device__ __forceinline__ void cp_async16(unsigned smem_addr, const void* gptr) {
    asm volatile("cp.async.cg.shared.global [%0], [%1], 16;"
                 :: "r"(smem_addr), "l"(gptr));
}
__device__ __forceinline__ void cp_commit() {
    asm volatile("cp.async.commit_group;");
}
template <int N>
__device__ __forceinline__ void cp_wait() {
    asm volatile("cp.async.wait_group %0;" :: "n"(N));
}

// ---------------------------------------------------------------------------
// Elementwise fp16 rounding pass (float4 -> 4 halves)
// ---------------------------------------------------------------------------
__global__ void round_fp16_kernel(const float* __restrict__ in,
                                  __half* __restrict__ out, int n4) {
    int i = blockIdx.x * blockDim.x + threadIdx.x;
    if (i < n4) {
        float4 v = ((const float4*)in)[i];
        __half2 h01 = __floats2half2_rn(v.x, v.y);
        __half2 h23 = __floats2half2_rn(v.z, v.w);
        __half2* o = (__half2*)(out + (size_t)i * 4);
        o[0] = h01; o[1] = h23;
    }
}

__global__ void zero_kernel(float* p, int n) {
    int i = blockIdx.x * blockDim.x + threadIdx.x;
    if (i < n) p[i] = 0.0f;
}

// ---------------------------------------------------------------------------
// fp16 GEMM (R6 config): C[M,1024] = A @ W^T + bias, optional elu+1,
// output fp32 (OUTH=0) or fp16 (OUTH=1).
// 256 threads, 8 warps (2x4), warp tile 64x32. cp.async double-buffered.
// k-reassignment: thread tg carries physical k = {4tg..4tg+3}.
// ---------------------------------------------------------------------------
#define BM 128
#define BN 128
#define BKH 32                    // k halves per chunk
#define SPADH 48                  // halves per smem row (96B)
#define TILEH (BM * SPADH)        // 6144 halves = 12288 B

template <int EPI, int OUTH>
__global__ void __launch_bounds__(256, 2)
gemm_fp16_kernel(const __half* __restrict__ A, const __half* __restrict__ W,
                 const float* __restrict__ bias, void* __restrict__ Cv) {
    __shared__ __half sh[4 * TILEH];          // [A0,A1,B0,B1] = 48 KB
    __half* Asm = sh;
    __half* Bsm = sh + 2 * TILEH;

    const int tid  = threadIdx.x;
    const int lane = tid & 31;
    const int warp = tid >> 5;
    const int wm   = (warp & 1) * 64;
    const int wn   = (warp >> 1) * 32;
    const int m0   = blockIdx.y * BM;
    const int n0   = blockIdx.x * BN;
    const int g    = lane >> 2;
    const int tg   = lane & 3;

    unsigned sbase = (unsigned)__cvta_generic_to_shared(sh);

    float acc[4][4][4];
#pragma unroll
    for (int mt = 0; mt < 4; mt++)
#pragma unroll
        for (int nt = 0; nt < 4; nt++)
#pragma unroll
            for (int i = 0; i < 4; i++) acc[mt][nt][i] = 0.0f;

    const int r0  = tid >> 2;          // rows r0, r0+64
    const int kc  = (tid & 3) * 8;
    const __half* Ap = A + (size_t)(m0 + r0) * DMODEL + kc;
    const __half* Wp = W + (size_t)(n0 + r0) * DMODEL + kc;
    const unsigned a_d0 = sbase + (r0 * SPADH + kc) * 2;
    const unsigned a_d1 = sbase + ((r0 + 64) * SPADH + kc) * 2;
    const unsigned b_d0 = a_d0 + 2 * TILEH * 2;
    const unsigned b_d1 = a_d1 + 2 * TILEH * 2;

    cp_async16(a_d0, Ap);
    cp_async16(a_d1, Ap + (size_t)64 * DMODEL);
    cp_async16(b_d0, Wp);
    cp_async16(b_d1, Wp + (size_t)64 * DMODEL);
    cp_commit();

    const int NK = DMODEL / BKH;   // 32 chunks
    for (int kt = 0; kt < NK; kt++) {
        const int buf = kt & 1;
        const unsigned nb = ((kt + 1) & 1) * TILEH * 2;
        if (kt + 1 < NK) {
            const __half* Apn = Ap + (kt + 1) * BKH;
            const __half* Wpn = Wp + (kt + 1) * BKH;
            cp_async16(a_d0 + nb, Apn);
            cp_async16(a_d1 + nb, Apn + (size_t)64 * DMODEL);
            cp_async16(b_d0 + nb, Wpn);
            cp_async16(b_d1 + nb, Wpn + (size_t)64 * DMODEL);
            cp_commit();
            cp_wait<1>();
        } else {
            cp_wait<0>();
        }
        __syncthreads();

        const __half* Ab = Asm + buf * TILEH;
        const __half* Bb = Bsm + buf * TILEH;
#pragma unroll
        for (int ks = 0; ks < 2; ks++) {
            const int kk = ks * 16 + 4 * tg;
            unsigned a[4][4], b[4][2];
#pragma unroll
            for (int mt = 0; mt < 4; mt++) {
                int base = (wm + mt * 16 + g) * SPADH + kk;
                uint2 lo = *(const uint2*)&Ab[base];
                uint2 hi = *(const uint2*)&Ab[base + 8 * SPADH];
                a[mt][0] = lo.x; a[mt][1] = hi.x; a[mt][2] = lo.y; a[mt][3] = hi.y;
            }
#pragma unroll
            for (int nt = 0; nt < 4; nt++) {
                uint2 bb = *(const uint2*)&Bb[(wn + nt * 8 + g) * SPADH + kk];
                b[nt][0] = bb.x; b[nt][1] = bb.y;
            }
#pragma unroll
            for (int mt = 0; mt < 4; mt++)
#pragma unroll
                for (int nt = 0; nt < 4; nt++)
                    mma_fp16(acc[mt][nt], a[mt], b[nt]);
        }
        __syncthreads();
    }

    // epilogue: bias + optional elu(x)+1
#pragma unroll
    for (int mt = 0; mt < 4; mt++) {
#pragma unroll
        for (int nt = 0; nt < 4; nt++) {
            int row = m0 + wm + mt * 16 + g;
            int col = n0 + wn + nt * 8 + 2 * tg;
            float bv0 = bias[col];
            float bv1 = bias[col + 1];
            float v00 = acc[mt][nt][0] + bv0;
            float v01 = acc[mt][nt][1] + bv1;
            float v10 = acc[mt][nt][2] + bv0;
            float v11 = acc[mt][nt][3] + bv1;
            if (EPI) {
                v00 = (v00 > 0.0f) ? v00 + 1.0f : expf(v00);
                v01 = (v01 > 0.0f) ? v01 + 1.0f : expf(v01);
                v10 = (v10 > 0.0f) ? v10 + 1.0f : expf(v10);
                v11 = (v11 > 0.0f) ? v11 + 1.0f : expf(v11);
            }
            if (OUTH) {
                __half* C = (__half*)Cv;
                *(__half2*)&C[(size_t)row * DMODEL + col]       = __floats2half2_rn(v00, v01);
                *(__half2*)&C[(size_t)(row + 8) * DMODEL + col] = __floats2half2_rn(v10, v11);
            } else {
                float* C = (float*)Cv;
                *(float2*)&C[(size_t)row * DMODEL + col]       = make_float2(v00, v01);
                *(float2*)&C[(size_t)(row + 8) * DMODEL + col] = make_float2(v10, v11);
            }
        }
    }
}

// ---------------------------------------------------------------------------
// KV chain (fp32 scalar): kv[b,h,i,j] = sum_s V[b,s,h,i] * K[b,s,h,j]
// ---------------------------------------------------------------------------
__global__ void __launch_bounds__(256)
kv_kernel(const float* __restrict__ K, const float* __restrict__ V,
          float* __restrict__ kv, float* __restrict__ ksum) {
    const int bh = blockIdx.x;
    const int b  = bh / NHEADS;
    const int h  = bh % NHEADS;
    const int tid = threadIdx.x;
    const int ty  = tid >> 4;
    const int tx  = tid & 15;

    __shared__ float Ks[16][64];
    __shared__ float Vs[16][64];

    float acc[4][4];
#pragma unroll
    for (int i = 0; i < 4; i++)
#pragma unroll
        for (int j = 0; j < 4; j++) acc[i][j] = 0.0f;
    float ks_acc = 0.0f;

    const float* Kbase = K + (size_t)b * S_LEN * DMODEL + h * DHEAD;
    const float* Vbase = V + (size_t)b * S_LEN * DMODEL + h * DHEAD;
    const int s0 = blockIdx.y * (S_LEN / 8);

    for (int s = s0; s < s0 + (S_LEN / 8); s += 16) {
        __syncthreads();
        {
            int r  = tid >> 4;
            int c4 = (tid & 15) << 2;
            *(float4*)&Ks[r][c4] = *(const float4*)&Kbase[(size_t)(s + r) * DMODEL + c4];
            *(float4*)&Vs[r][c4] = *(const float4*)&Vbase[(size_t)(s + r) * DMODEL + c4];
        }
        __syncthreads();
        if (tid < 64) {
#pragma unroll
            for (int ss = 0; ss < 16; ss++) ks_acc += Ks[ss][tid];
        }
#pragma unroll
        for (int ss = 0; ss < 16; ss++) {
            float vr[4], kr[4];
#pragma unroll
            for (int i = 0; i < 4; i++) vr[i] = Vs[ss][ty * 4 + i];
#pragma unroll
            for (int j = 0; j < 4; j++) kr[j] = Ks[ss][tx * 4 + j];
#pragma unroll
            for (int i = 0; i < 4; i++)
#pragma unroll
                for (int j = 0; j < 4; j++) acc[i][j] += vr[i] * kr[j];
        }
    }

    float* kvbh = kv + (size_t)bh * DHEAD * DHEAD;
#pragma unroll
    for (int i = 0; i < 4; i++)
#pragma unroll
        for (int j = 0; j < 4; j++)
            atomicAdd(&kvbh[(ty * 4 + i) * DHEAD + tx * 4 + j], acc[i][j]);
    if (tid < 64) atomicAdd(&ksum[bh * DHEAD + tid], ks_acc);
}

// ---------------------------------------------------------------------------
// Tensor-core attention apply:
// out[t, h*64+i] = norm(t,h) * sum_d q[t,h,d] * kv[b,h,i,d]  -> fp16
// Block: 128 t-rows x 1 head; 256 threads, 8 warps x 16-row m-tiles.
// ---------------------------------------------------------------------------
#define APAD 80   // halves per smem row

__global__ void __launch_bounds__(256)
attn_mma_kernel(const __half* __restrict__ Qf, const __half* __restrict__ kvh,
                const float* __restrict__ ksum, __half* __restrict__ attn) {
    const int h  = blockIdx.y;
    const int t0 = blockIdx.x * 128;
    const int b  = t0 / S_LEN;
    const int bh = b * NHEADS + h;
    const int tid  = threadIdx.x;
    const int lane = tid & 31;
    const int warp = tid >> 5;
    const int g    = lane >> 2;
    const int tg   = lane & 3;
    const int wm   = warp * 16;

    __shared__ __half Qs[128 * APAD];
    __shared__ __half Bs[64 * APAD];
    __shared__ float  kss[64];
    __shared__ float  nrm[128];

    // load Q tile [128][64] halves
#pragma unroll
    for (int i = 0; i < 4; i++) {
        int idx = tid + 256 * i;
        int r = idx >> 3, c8 = (idx & 7) * 8;
        *(uint4*)&Qs[r * APAD + c8] =
            *(const uint4*)&Qf[(size_t)(t0 + r) * DMODEL + h * DHEAD + c8];
    }
    // load kvh tile [64][64]
#pragma unroll
    for (int i = 0; i < 2; i++) {
        int idx = tid + 256 * i;
        int r = idx >> 3, c8 = (idx & 7) * 8;
        *(uint4*)&Bs[r * APAD + c8] =
            *(const uint4*)&kvh[(size_t)bh * DHEAD * DHEAD + r * DHEAD + c8];
    }
    if (tid < 64) kss[tid] = ksum[bh * DHEAD + tid];
    __syncthreads();

    // norm per row: 2 threads per row, 32 d each
    {
        int row = tid >> 1;
        int half_ = tid & 1;
        float nd = 0.0f;
        const __half* qr = &Qs[row * APAD + half_ * 32];
        const float* ks_ = &kss[half_ * 32];
#pragma unroll
        for (int d = 0; d < 32; d++) nd += __half2float(qr[d]) * ks_[d];
        nd += __shfl_xor_sync(0xFFFFFFFF, nd, 1);
        if (half_ == 0) nrm[row] = 1.0f / (nd + 1e-6f);
    }
    __syncthreads();

    float acc[8][4];
#pragma unroll
    for (int nt = 0; nt < 8; nt++)
#pragma unroll
        for (int i = 0; i < 4; i++) acc[nt][i] = 0.0f;

#pragma unroll
    for (int ks = 0; ks < 4; ks++) {
        const int kk = ks * 16 + 4 * tg;
        unsigned a[4], bfr[8][2];
        {
            int base = (wm + g) * APAD + kk;
            uint2 lo = *(const uint2*)&Qs[base];
            uint2 hi = *(const uint2*)&Qs[base + 8 * APAD];
            a[0] = lo.x; a[1] = hi.x; a[2] = lo.y; a[3] = hi.y;
        }
#pragma unroll
        for (int nt = 0; nt < 8; nt++) {
            uint2 bb = *(const uint2*)&Bs[(nt * 8 + g) * APAD + kk];
            bfr[nt][0] = bb.x; bfr[nt][1] = bb.y;
        }
#pragma unroll
        for (int nt = 0; nt < 8; nt++)
            mma_fp16(acc[nt], a, bfr[nt]);
    }

    // scale by norm and store fp16
    const float n0 = nrm[wm + g];
    const float n1 = nrm[wm + g + 8];
    __half* op = attn + (size_t)(t0 + wm + g) * DMODEL + h * DHEAD;
    __half* op8 = op + (size_t)8 * DMODEL;
#pragma unroll
    for (int nt = 0; nt < 8; nt++) {
        int col = nt * 8 + 2 * tg;
        *(__half2*)&op[col]  = __floats2half2_rn(acc[nt][0] * n0, acc[nt][1] * n0);
        *(__half2*)&op8[col] = __floats2half2_rn(acc[nt][2] * n1, acc[nt][3] * n1);
    }
}

// ---------------------------------------------------------------------------
// Launch
// ---------------------------------------------------------------------------
extern "C" void kernel_launch(void* const* d_in, const int* in_sizes, int n_in,
                              void* d_out, int out_size) {
    const float* query = (const float*)d_in[0];
    const float* key_  = (const float*)d_in[1];
    const float* value = (const float*)d_in[2];
    const float* Wq = (const float*)d_in[3];
    const float* bq = (const float*)d_in[4];
    const float* Wk = (const float*)d_in[5];
    const float* bk = (const float*)d_in[6];
    const float* Wv = (const float*)d_in[7];
    const float* bv = (const float*)d_in[8];
    const float* Wo = (const float*)d_in[9];
    const float* bo = (const float*)d_in[10];
    float* out = (float*)d_out;

    float *kf, *vf, *kv, *ks;
    __half *fq, *hq, *hk, *hv, *hattn, *hw, *kvh;
    cudaGetSymbolAddress((void**)&kf,    g_k);
    cudaGetSymbolAddress((void**)&vf,    g_v);
    cudaGetSymbolAddress((void**)&kv,    g_kv);
    cudaGetSymbolAddress((void**)&kvh,   g_kvh);
    cudaGetSymbolAddress((void**)&ks,    g_ksum);
    cudaGetSymbolAddress((void**)&fq,    g_fq);
    cudaGetSymbolAddress((void**)&hq,    g_hq);
    cudaGetSymbolAddress((void**)&hk,    g_hk);
    cudaGetSymbolAddress((void**)&hv,    g_hv);
    cudaGetSymbolAddress((void**)&hattn, g_hattn);
    cudaGetSymbolAddress((void**)&hw,    g_hw);
    __half* hwq = hw;
    __half* hwk = hw + (size_t)DMODEL * DMODEL;
    __half* hwv = hw + (size_t)2 * DMODEL * DMODEL;
    __half* hwo = hw + (size_t)3 * DMODEL * DMODEL;

    // fp16 pre-rounding passes
    const int N4_IN = (NROWS * DMODEL) / 4;
    const int N4_W  = (DMODEL * DMODEL) / 4;
    round_fp16_kernel<<<N4_IN / 256, 256>>>(query, hq, N4_IN);
    round_fp16_kernel<<<N4_IN / 256, 256>>>(key_,  hk, N4_IN);
    round_fp16_kernel<<<N4_IN / 256, 256>>>(value, hv, N4_IN);
    round_fp16_kernel<<<N4_W / 256, 256>>>(Wq, hwq, N4_W);
    round_fp16_kernel<<<N4_W / 256, 256>>>(Wk, hwk, N4_W);
    round_fp16_kernel<<<N4_W / 256, 256>>>(Wv, hwv, N4_W);
    round_fp16_kernel<<<N4_W / 256, 256>>>(Wo, hwo, N4_W);

    // zero accumulators for atomics
    zero_kernel<<<(BATCH * NHEADS * DHEAD * DHEAD + 255) / 256, 256>>>(kv, BATCH * NHEADS * DHEAD * DHEAD);
    zero_kernel<<<(BATCH * NHEADS * DHEAD + 255) / 256, 256>>>(ks, BATCH * NHEADS * DHEAD);

    dim3 gemm_grid(DMODEL / BN, NROWS / BM);  // (8, 256)
    gemm_fp16_kernel<1, 1><<<gemm_grid, 256>>>(hq, hwq, bq, fq);   // Q -> fp16 features
    gemm_fp16_kernel<1, 0><<<gemm_grid, 256>>>(hk, hwk, bk, kf);   // K -> fp32
    gemm_fp16_kernel<0, 0><<<gemm_grid, 256>>>(hv, hwv, bv, vf);   // V -> fp32

    kv_kernel<<<dim3(BATCH * NHEADS, 8), 256>>>(kf, vf, kv, ks);

    // round kv to fp16 for tensor-core attention
    round_fp16_kernel<<<(BATCH * NHEADS * DHEAD * DHEAD / 4 + 255) / 256, 256>>>(
        kv, kvh, BATCH * NHEADS * DHEAD * DHEAD / 4);

    attn_mma_kernel<<<dim3(NROWS / 128, NHEADS), 256>>>(fq, kvh, ks, hattn);

    gemm_fp16_kernel<0, 0><<<gemm_grid, 256>>>(hattn, hwo, bo, out);
}

// round 9
// speedup vs baseline: 1.3449x; 1.3449x over previous
#include <cuda_runtime.h>
#include <cuda_fp16.h>
#include <math.h>
#include <stdint.h>

#define S_LEN   8192
#define BATCH   4
#define DMODEL  1024
#define NROWS   (BATCH * S_LEN)   // 32768
#define NHEADS  16
#define DHEAD   64

// Scratch (device globals: allocation-free per harness rules)
__device__ float  g_q[(size_t)NROWS * DMODEL];    // fp32 Q features
__device__ float  g_k[(size_t)NROWS * DMODEL];    // fp32 K features
__device__ float  g_v[(size_t)NROWS * DMODEL];    // fp32 V
__device__ __half g_hq[(size_t)NROWS * DMODEL];   // fp16-rounded inputs
__device__ __half g_hk[(size_t)NROWS * DMODEL];
__device__ __half g_hv[(size_t)NROWS * DMODEL];
__device__ __half g_hattn[(size_t)NROWS * DMODEL];
__device__ __half g_hw[4][DMODEL * DMODEL];       // fp16-rounded weights
__device__ float  g_kv[BATCH * NHEADS * DHEAD * DHEAD];   // [b,h,dv,dk]
__device__ float  g_ksum[BATCH * NHEADS * DHEAD];

// ---------------------------------------------------------------------------
// helpers
// ---------------------------------------------------------------------------
__device__ __forceinline__ void mma_fp16(float* c, const unsigned* a, const unsigned* b) {
    asm volatile(
        "mma.sync.aligned.m16n8k16.row.col.f32.f16.f16.f32 "
        "{%0,%1,%2,%3}, {%4,%5,%6,%7}, {%8,%9}, {%0,%1,%2,%3};"
        : "+f"(c[0]), "+f"(c[1]), "+f"(c[2]), "+f"(c[3])
        : "r"(a[0]), "r"(a[1]), "r"(a[2]), "r"(a[3]), "r"(b[0]), "r"(b[1]));
}

__device__ __forceinline__ void cp_async16(unsigned smem_addr, const void* gptr) {
    asm volatile("cp.async.cg.shared.global [%0], [%1], 16;"
                 :: "r"(smem_addr), "l"(gptr));
}
__device__ __forceinline__ void cp_commit() {
    asm volatile("cp.async.commit_group;");
}
template <int N>
__device__ __forceinline__ void cp_wait() {
    asm volatile("cp.async.wait_group %0;" :: "n"(N));
}

// ---------------------------------------------------------------------------
// Elementwise fp16 rounding pass (float4 -> 4 halves)
// ---------------------------------------------------------------------------
__global__ void round_fp16_kernel(const float* __restrict__ in,
                                  __half* __restrict__ out, int n4) {
    int i = blockIdx.x * blockDim.x + threadIdx.x;
    if (i < n4) {
        float4 v = ((const float4*)in)[i];
        __half2 h01 = __floats2half2_rn(v.x, v.y);
        __half2 h23 = __floats2half2_rn(v.z, v.w);
        __half2* o = (__half2*)(out + (size_t)i * 4);
        o[0] = h01; o[1] = h23;
    }
}

__global__ void zero_kernel(float* p, int n) {
    int i = blockIdx.x * blockDim.x + threadIdx.x;
    if (i < n) p[i] = 0.0f;
}

// ---------------------------------------------------------------------------
// fp16 GEMM: C[M,1024] = A[M,1024] @ W[1024,1024]^T + bias, optional elu+1.
// 256 threads, 8 warps (2x4), warp tile 64x32 (R6 proven config).
// 3-stage cp.async pipeline, ONE barrier per k-chunk:
//   wait<1>; __syncthreads(); fill(kt+2); commit; compute(kt)
// The sync both publishes chunk kt and protects the stage being overwritten
// (fill(kt+2) targets the stage read at kt-1). One commit per iteration
// (possibly empty) keeps wait<1> exact.
// k-reassignment: thread tg carries physical k = {4tg..4tg+3} for both
// operands -> conflict-free LDS.64 with SPADH=48.
// ---------------------------------------------------------------------------
#define BM 128
#define BN 128
#define BKH 32                    // k halves per chunk
#define SPADH 48                  // halves per smem row (96B)
#define TILEH (BM * SPADH)        // 6144 halves = 12288 B
#define NSTAGE 3
#define GEMM_SMEM_BYTES (2 * NSTAGE * TILEH * 2)   // 73728 B

template <int EPI>
__global__ void __launch_bounds__(256, 2)
gemm_fp16_kernel(const __half* __restrict__ A, const __half* __restrict__ W,
                 const float* __restrict__ bias, float* __restrict__ C) {
    extern __shared__ __half sh[];            // [A0,A1,A2,B0,B1,B2]
    __half* Asm = sh;
    __half* Bsm = sh + NSTAGE * TILEH;

    const int tid  = threadIdx.x;
    const int lane = tid & 31;
    const int warp = tid >> 5;
    const int wm   = (warp & 1) * 64;
    const int wn   = (warp >> 1) * 32;
    const int m0   = blockIdx.y * BM;
    const int n0   = blockIdx.x * BN;
    const int g    = lane >> 2;
    const int tg   = lane & 3;

    unsigned sbase = (unsigned)__cvta_generic_to_shared(sh);

    float acc[4][4][4];
#pragma unroll
    for (int mt = 0; mt < 4; mt++)
#pragma unroll
        for (int nt = 0; nt < 4; nt++)
#pragma unroll
            for (int i = 0; i < 4; i++) acc[mt][nt][i] = 0.0f;

    const int r0  = tid >> 2;          // rows r0, r0+64
    const int kc  = (tid & 3) * 8;
    const __half* Ap = A + (size_t)(m0 + r0) * DMODEL + kc;
    const __half* Wp = W + (size_t)(n0 + r0) * DMODEL + kc;
    const unsigned a_d0 = sbase + (r0 * SPADH + kc) * 2;
    const unsigned a_d1 = sbase + ((r0 + 64) * SPADH + kc) * 2;
    const unsigned b_d0 = a_d0 + NSTAGE * TILEH * 2;
    const unsigned b_d1 = a_d1 + NSTAGE * TILEH * 2;

    const int NK = DMODEL / BKH;   // 32 chunks

    // fill chunk c into stage c % NSTAGE
    auto fill = [&](int c) {
        const unsigned so = (unsigned)(c % NSTAGE) * TILEH * 2;
        const __half* Apn = Ap + c * BKH;
        const __half* Wpn = Wp + c * BKH;
        cp_async16(a_d0 + so, Apn);
        cp_async16(a_d1 + so, Apn + (size_t)64 * DMODEL);
        cp_async16(b_d0 + so, Wpn);
        cp_async16(b_d1 + so, Wpn + (size_t)64 * DMODEL);
    };

    // prologue: chunks 0, 1 (one commit each)
    fill(0); cp_commit();
    fill(1); cp_commit();

    for (int kt = 0; kt < NK; kt++) {
        cp_wait<1>();          // chunk kt arrived (commit kt done, kt+1 may pend)
        __syncthreads();       // publish fills + all warps done reading stage (kt-1)%3

        if (kt + 2 < NK) fill(kt + 2);
        cp_commit();           // always one commit per iteration

        const int buf = kt % NSTAGE;
        const __half* Ab = Asm + buf * TILEH;
        const __half* Bb = Bsm + buf * TILEH;
#pragma unroll
        for (int ks = 0; ks < 2; ks++) {
            const int kk = ks * 16 + 4 * tg;
            unsigned a[4][4], b[4][2];
#pragma unroll
            for (int mt = 0; mt < 4; mt++) {
                int base = (wm + mt * 16 + g) * SPADH + kk;
                uint2 lo = *(const uint2*)&Ab[base];
                uint2 hi = *(const uint2*)&Ab[base + 8 * SPADH];
                a[mt][0] = lo.x; a[mt][1] = hi.x; a[mt][2] = lo.y; a[mt][3] = hi.y;
            }
#pragma unroll
            for (int nt = 0; nt < 4; nt++) {
                uint2 bb = *(const uint2*)&Bb[(wn + nt * 8 + g) * SPADH + kk];
                b[nt][0] = bb.x; b[nt][1] = bb.y;
            }
#pragma unroll
            for (int mt = 0; mt < 4; mt++)
#pragma unroll
                for (int nt = 0; nt < 4; nt++)
                    mma_fp16(acc[mt][nt], a[mt], b[nt]);
        }
    }

    // epilogue: bias + optional elu(x)+1, float2 stores
#pragma unroll
    for (int mt = 0; mt < 4; mt++) {
#pragma unroll
        for (int nt = 0; nt < 4; nt++) {
            int row = m0 + wm + mt * 16 + g;
            int col = n0 + wn + nt * 8 + 2 * tg;
            float bv0 = bias[col];
            float bv1 = bias[col + 1];
            float v00 = acc[mt][nt][0] + bv0;
            float v01 = acc[mt][nt][1] + bv1;
            float v10 = acc[mt][nt][2] + bv0;
            float v11 = acc[mt][nt][3] + bv1;
            if (EPI) {
                v00 = (v00 > 0.0f) ? v00 + 1.0f : expf(v00);
                v01 = (v01 > 0.0f) ? v01 + 1.0f : expf(v01);
                v10 = (v10 > 0.0f) ? v10 + 1.0f : expf(v10);
                v11 = (v11 > 0.0f) ? v11 + 1.0f : expf(v11);
            }
            *(float2*)&C[(size_t)row * DMODEL + col]       = make_float2(v00, v01);
            *(float2*)&C[(size_t)(row + 8) * DMODEL + col] = make_float2(v10, v11);
        }
    }
}

// ---------------------------------------------------------------------------
// KV chain: kv[b,h,i,j] = sum_s V[b,s,h,i] * K[b,s,h,j];  ksum[b,h,j] = sum_s K
// ---------------------------------------------------------------------------
__global__ void __launch_bounds__(256)
kv_kernel(const float* __restrict__ K, const float* __restrict__ V,
          float* __restrict__ kv, float* __restrict__ ksum) {
    const int bh = blockIdx.x;
    const int b  = bh / NHEADS;
    const int h  = bh % NHEADS;
    const int tid = threadIdx.x;
    const int ty  = tid >> 4;
    const int tx  = tid & 15;

    __shared__ float Ks[16][64];
    __shared__ float Vs[16][64];

    float acc[4][4];
#pragma unroll
    for (int i = 0; i < 4; i++)
#pragma unroll
        for (int j = 0; j < 4; j++) acc[i][j] = 0.0f;
    float ks_acc = 0.0f;

    const float* Kbase = K + (size_t)b * S_LEN * DMODEL + h * DHEAD;
    const float* Vbase = V + (size_t)b * S_LEN * DMODEL + h * DHEAD;
    const int s0 = blockIdx.y * (S_LEN / 8);

    for (int s = s0; s < s0 + (S_LEN / 8); s += 16) {
        __syncthreads();
        {
            int r  = tid >> 4;
            int c4 = (tid & 15) << 2;
            *(float4*)&Ks[r][c4] = *(const float4*)&Kbase[(size_t)(s + r) * DMODEL + c4];
            *(float4*)&Vs[r][c4] = *(const float4*)&Vbase[(size_t)(s + r) * DMODEL + c4];
        }
        __syncthreads();
        if (tid < 64) {
#pragma unroll
            for (int ss = 0; ss < 16; ss++) ks_acc += Ks[ss][tid];
        }
#pragma unroll
        for (int ss = 0; ss < 16; ss++) {
            float vr[4], kr[4];
#pragma unroll
            for (int i = 0; i < 4; i++) vr[i] = Vs[ss][ty * 4 + i];
#pragma unroll
            for (int j = 0; j < 4; j++) kr[j] = Ks[ss][tx * 4 + j];
#pragma unroll
            for (int i = 0; i < 4; i++)
#pragma unroll
                for (int j = 0; j < 4; j++) acc[i][j] += vr[i] * kr[j];
        }
    }

    float* kvbh = kv + (size_t)bh * DHEAD * DHEAD;
#pragma unroll
    for (int i = 0; i < 4; i++)
#pragma unroll
        for (int j = 0; j < 4; j++)
            atomicAdd(&kvbh[(ty * 4 + i) * DHEAD + tx * 4 + j], acc[i][j]);
    if (tid < 64) atomicAdd(&ksum[bh * DHEAD + tid], ks_acc);
}

// ---------------------------------------------------------------------------
// Attention apply; output rounded to fp16 for the final GEMM
// ---------------------------------------------------------------------------
__global__ void __launch_bounds__(128)
attn_kernel(const float* __restrict__ Q, const float* __restrict__ kv,
            const float* __restrict__ ksum, __half* __restrict__ attn) {
    const int h   = blockIdx.y;
    const int row = blockIdx.x * 128 + threadIdx.x;
    const int b   = row / S_LEN;

    __shared__ float kvs[64][64];
    __shared__ float kss[64];

    const float* kvsrc = kv + (size_t)(b * NHEADS + h) * DHEAD * DHEAD;
    for (int i = threadIdx.x; i < (DHEAD * DHEAD) / 4; i += 128)
        ((float4*)kvs)[i] = ((const float4*)kvsrc)[i];
    if (threadIdx.x < 64) kss[threadIdx.x] = ksum[(b * NHEADS + h) * DHEAD + threadIdx.x];
    __syncthreads();

    float q[64];
    const float* qp = Q + (size_t)row * DMODEL + h * DHEAD;
#pragma unroll
    for (int i = 0; i < 16; i++) ((float4*)q)[i] = ((const float4*)qp)[i];

    float nd = 0.0f;
#pragma unroll
    for (int d = 0; d < 64; d++) nd += q[d] * kss[d];
    const float norm = 1.0f / (nd + 1e-6f);

    __half* op = attn + (size_t)row * DMODEL + h * DHEAD;
    for (int i0 = 0; i0 < 64; i0 += 4) {
        float out[4];
#pragma unroll
        for (int u = 0; u < 4; u++) {
            float s = 0.0f;
            const float4* kv4 = (const float4*)kvs[i0 + u];
#pragma unroll
            for (int d4 = 0; d4 < 16; d4++) {
                float4 kvv = kv4[d4];
                s += q[4*d4] * kvv.x + q[4*d4+1] * kvv.y
                   + q[4*d4+2] * kvv.z + q[4*d4+3] * kvv.w;
            }
            out[u] = s * norm;
        }
        __half2 h01 = __floats2half2_rn(out[0], out[1]);
        __half2 h23 = __floats2half2_rn(out[2], out[3]);
        *(__half2*)&op[i0]     = h01;
        *(__half2*)&op[i0 + 2] = h23;
    }
}

// ---------------------------------------------------------------------------
// Launch
// ---------------------------------------------------------------------------
extern "C" void kernel_launch(void* const* d_in, const int* in_sizes, int n_in,
                              void* d_out, int out_size) {
    const float* query = (const float*)d_in[0];
    const float* key_  = (const float*)d_in[1];
    const float* value = (const float*)d_in[2];
    const float* Wq = (const float*)d_in[3];
    const float* bq = (const float*)d_in[4];
    const float* Wk = (const float*)d_in[5];
    const float* bk = (const float*)d_in[6];
    const float* Wv = (const float*)d_in[7];
    const float* bv = (const float*)d_in[8];
    const float* Wo = (const float*)d_in[9];
    const float* bo = (const float*)d_in[10];
    float* out = (float*)d_out;

    float *qf, *kf, *vf, *kv, *ks;
    __half *hq, *hk, *hv, *hattn, *hw;
    cudaGetSymbolAddress((void**)&qf,    g_q);
    cudaGetSymbolAddress((void**)&kf,    g_k);
    cudaGetSymbolAddress((void**)&vf,    g_v);
    cudaGetSymbolAddress((void**)&kv,    g_kv);
    cudaGetSymbolAddress((void**)&ks,    g_ksum);
    cudaGetSymbolAddress((void**)&hq,    g_hq);
    cudaGetSymbolAddress((void**)&hk,    g_hk);
    cudaGetSymbolAddress((void**)&hv,    g_hv);
    cudaGetSymbolAddress((void**)&hattn, g_hattn);
    cudaGetSymbolAddress((void**)&hw,    g_hw);
    __half* hwq = hw;
    __half* hwk = hw + (size_t)DMODEL * DMODEL;
    __half* hwv = hw + (size_t)2 * DMODEL * DMODEL;
    __half* hwo = hw + (size_t)3 * DMODEL * DMODEL;

    static int smem_set = 0;
    if (!smem_set) {
        cudaFuncSetAttribute(gemm_fp16_kernel<1>,
                             cudaFuncAttributeMaxDynamicSharedMemorySize, GEMM_SMEM_BYTES);
        cudaFuncSetAttribute(gemm_fp16_kernel<0>,
                             cudaFuncAttributeMaxDynamicSharedMemorySize, GEMM_SMEM_BYTES);
        smem_set = 1;
    }

    // fp16 pre-rounding passes
    const int N4_IN = (NROWS * DMODEL) / 4;
    const int N4_W  = (DMODEL * DMODEL) / 4;
    round_fp16_kernel<<<N4_IN / 256, 256>>>(query, hq, N4_IN);
    round_fp16_kernel<<<N4_IN / 256, 256>>>(key_,  hk, N4_IN);
    round_fp16_kernel<<<N4_IN / 256, 256>>>(value, hv, N4_IN);
    round_fp16_kernel<<<N4_W / 256, 256>>>(Wq, hwq, N4_W);
    round_fp16_kernel<<<N4_W / 256, 256>>>(Wk, hwk, N4_W);
    round_fp16_kernel<<<N4_W / 256, 256>>>(Wv, hwv, N4_W);
    round_fp16_kernel<<<N4_W / 256, 256>>>(Wo, hwo, N4_W);

    // zero accumulators for atomics
    zero_kernel<<<(BATCH * NHEADS * DHEAD * DHEAD + 255) / 256, 256>>>(kv, BATCH * NHEADS * DHEAD * DHEAD);
    zero_kernel<<<(BATCH * NHEADS * DHEAD + 255) / 256, 256>>>(ks, BATCH * NHEADS * DHEAD);

    dim3 gemm_grid(DMODEL / BN, NROWS / BM);  // (8, 256)
    gemm_fp16_kernel<1><<<gemm_grid, 256, GEMM_SMEM_BYTES>>>(hq, hwq, bq, qf);
    gemm_fp16_kernel<1><<<gemm_grid, 256, GEMM_SMEM_BYTES>>>(hk, hwk, bk, kf);
    gemm_fp16_kernel<0><<<gemm_grid, 256, GEMM_SMEM_BYTES>>>(hv, hwv, bv, vf);

    kv_kernel<<<dim3(BATCH * NHEADS, 8), 256>>>(kf, vf, kv, ks);

    attn_kernel<<<dim3(NROWS / 128, NHEADS), 128>>>(qf, kv, ks, hattn);

    gemm_fp16_kernel<0><<<gemm_grid, 256, GEMM_SMEM_BYTES>>>(hattn, hwo, bo, out);
}

// round 10
// speedup vs baseline: 1.3474x; 1.0018x over previous
#include <cuda_runtime.h>
#include <cuda_fp16.h>
#include <math.h>
#include <stdint.h>

#define S_LEN   8192
#define BATCH   4
#define DMODEL  1024
#define NROWS   (BATCH * S_LEN)   // 32768
#define NHEADS  16
#define DHEAD   64

// Scratch (device globals: allocation-free per harness rules)
__device__ float  g_q[(size_t)NROWS * DMODEL];    // fp32 Q features
__device__ float  g_k[(size_t)NROWS * DMODEL];    // fp32 K features
__device__ float  g_v[(size_t)NROWS * DMODEL];    // fp32 V
__device__ __half g_hq[(size_t)NROWS * DMODEL];   // fp16-rounded inputs
__device__ __half g_hk[(size_t)NROWS * DMODEL];
__device__ __half g_hv[(size_t)NROWS * DMODEL];
__device__ __half g_hattn[(size_t)NROWS * DMODEL];
__device__ __half g_hw[4][DMODEL * DMODEL];       // fp16-rounded weights
__device__ float  g_kv[BATCH * NHEADS * DHEAD * DHEAD];   // [b,h,dv,dk]
__device__ float  g_ksum[BATCH * NHEADS * DHEAD];

// ---------------------------------------------------------------------------
// helpers
// ---------------------------------------------------------------------------
__device__ __forceinline__ void mma_fp16(float* c, const unsigned* a, const unsigned* b) {
    asm volatile(
        "mma.sync.aligned.m16n8k16.row.col.f32.f16.f16.f32 "
        "{%0,%1,%2,%3}, {%4,%5,%6,%7}, {%8,%9}, {%0,%1,%2,%3};"
        : "+f"(c[0]), "+f"(c[1]), "+f"(c[2]), "+f"(c[3])
        : "r"(a[0]), "r"(a[1]), "r"(a[2]), "r"(a[3]), "r"(b[0]), "r"(b[1]));
}

__device__ __forceinline__ void cp_async16(unsigned smem_addr, const void* gptr) {
    asm volatile("cp.async.cg.shared.global [%0], [%1], 16;"
                 :: "r"(smem_addr), "l"(gptr));
}
__device__ __forceinline__ void cp_commit() {
    asm volatile("cp.async.commit_group;");
}
template <int N>
__device__ __forceinline__ void cp_wait() {
    asm volatile("cp.async.wait_group %0;" :: "n"(N));
}

// ---------------------------------------------------------------------------
// Elementwise fp16 rounding pass (float4 -> 4 halves)
// ---------------------------------------------------------------------------
__global__ void round_fp16_kernel(const float* __restrict__ in,
                                  __half* __restrict__ out, int n4) {
    int i = blockIdx.x * blockDim.x + threadIdx.x;
    if (i < n4) {
        float4 v = ((const float4*)in)[i];
        __half2 h01 = __floats2half2_rn(v.x, v.y);
        __half2 h23 = __floats2half2_rn(v.z, v.w);
        __half2* o = (__half2*)(out + (size_t)i * 4);
        o[0] = h01; o[1] = h23;
    }
}

__global__ void zero_kernel(float* p, int n) {
    int i = blockIdx.x * blockDim.x + threadIdx.x;
    if (i < n) p[i] = 0.0f;
}

// ---------------------------------------------------------------------------
// fp16 GEMM: C[M,1024] = A[M,1024] @ W[1024,1024]^T + bias, optional elu+1.
// 256 threads, 8 warps (2x4), warp tile 64x32 (R6 proven config).
// 3-stage cp.async pipeline, ONE barrier per k-chunk:
//   wait<1>; __syncthreads(); fill(kt+2); commit; compute(kt)
// The sync both publishes chunk kt and protects the stage being overwritten
// (fill(kt+2) targets the stage read at kt-1). One commit per iteration
// (possibly empty) keeps wait<1> exact.
// k-reassignment: thread tg carries physical k = {4tg..4tg+3} for both
// operands -> conflict-free LDS.64 with SPADH=48.
// ---------------------------------------------------------------------------
#define BM 128
#define BN 128
#define BKH 32                    // k halves per chunk
#define SPADH 48                  // halves per smem row (96B)
#define TILEH (BM * SPADH)        // 6144 halves = 12288 B
#define NSTAGE 3
#define GEMM_SMEM_BYTES (2 * NSTAGE * TILEH * 2)   // 73728 B

template <int EPI>
__global__ void __launch_bounds__(256, 2)
gemm_fp16_kernel(const __half* __restrict__ A, const __half* __restrict__ W,
                 const float* __restrict__ bias, float* __restrict__ C) {
    extern __shared__ __half sh[];            // [A0,A1,A2,B0,B1,B2]
    __half* Asm = sh;
    __half* Bsm = sh + NSTAGE * TILEH;

    const int tid  = threadIdx.x;
    const int lane = tid & 31;
    const int warp = tid >> 5;
    const int wm   = (warp & 1) * 64;
    const int wn   = (warp >> 1) * 32;
    const int m0   = blockIdx.y * BM;
    const int n0   = blockIdx.x * BN;
    const int g    = lane >> 2;
    const int tg   = lane & 3;

    unsigned sbase = (unsigned)__cvta_generic_to_shared(sh);

    float acc[4][4][4];
#pragma unroll
    for (int mt = 0; mt < 4; mt++)
#pragma unroll
        for (int nt = 0; nt < 4; nt++)
#pragma unroll
            for (int i = 0; i < 4; i++) acc[mt][nt][i] = 0.0f;

    const int r0  = tid >> 2;          // rows r0, r0+64
    const int kc  = (tid & 3) * 8;
    const __half* Ap = A + (size_t)(m0 + r0) * DMODEL + kc;
    const __half* Wp = W + (size_t)(n0 + r0) * DMODEL + kc;
    const unsigned a_d0 = sbase + (r0 * SPADH + kc) * 2;
    const unsigned a_d1 = sbase + ((r0 + 64) * SPADH + kc) * 2;
    const unsigned b_d0 = a_d0 + NSTAGE * TILEH * 2;
    const unsigned b_d1 = a_d1 + NSTAGE * TILEH * 2;

    const int NK = DMODEL / BKH;   // 32 chunks

    // fill chunk c into stage c % NSTAGE
    auto fill = [&](int c) {
        const unsigned so = (unsigned)(c % NSTAGE) * TILEH * 2;
        const __half* Apn = Ap + c * BKH;
        const __half* Wpn = Wp + c * BKH;
        cp_async16(a_d0 + so, Apn);
        cp_async16(a_d1 + so, Apn + (size_t)64 * DMODEL);
        cp_async16(b_d0 + so, Wpn);
        cp_async16(b_d1 + so, Wpn + (size_t)64 * DMODEL);
    };

    // prologue: chunks 0, 1 (one commit each)
    fill(0); cp_commit();
    fill(1); cp_commit();

    for (int kt = 0; kt < NK; kt++) {
        cp_wait<1>();          // chunk kt arrived (commit kt done, kt+1 may pend)
        __syncthreads();       // publish fills + all warps done reading stage (kt-1)%3

        if (kt + 2 < NK) fill(kt + 2);
        cp_commit();           // always one commit per iteration

        const int buf = kt % NSTAGE;
        const __half* Ab = Asm + buf * TILEH;
        const __half* Bb = Bsm + buf * TILEH;
#pragma unroll
        for (int ks = 0; ks < 2; ks++) {
            const int kk = ks * 16 + 4 * tg;
            unsigned a[4][4], b[4][2];
#pragma unroll
            for (int mt = 0; mt < 4; mt++) {
                int base = (wm + mt * 16 + g) * SPADH + kk;
                uint2 lo = *(const uint2*)&Ab[base];
                uint2 hi = *(const uint2*)&Ab[base + 8 * SPADH];
                a[mt][0] = lo.x; a[mt][1] = hi.x; a[mt][2] = lo.y; a[mt][3] = hi.y;
            }
#pragma unroll
            for (int nt = 0; nt < 4; nt++) {
                uint2 bb = *(const uint2*)&Bb[(wn + nt * 8 + g) * SPADH + kk];
                b[nt][0] = bb.x; b[nt][1] = bb.y;
            }
#pragma unroll
            for (int mt = 0; mt < 4; mt++)
#pragma unroll
                for (int nt = 0; nt < 4; nt++)
                    mma_fp16(acc[mt][nt], a[mt], b[nt]);
        }
    }

    // epilogue: bias + optional elu(x)+1, float2 stores
#pragma unroll
    for (int mt = 0; mt < 4; mt++) {
#pragma unroll
        for (int nt = 0; nt < 4; nt++) {
            int row = m0 + wm + mt * 16 + g;
            int col = n0 + wn + nt * 8 + 2 * tg;
            float bv0 = bias[col];
            float bv1 = bias[col + 1];
            float v00 = acc[mt][nt][0] + bv0;
            float v01 = acc[mt][nt][1] + bv1;
            float v10 = acc[mt][nt][2] + bv0;
            float v11 = acc[mt][nt][3] + bv1;
            if (EPI) {
                v00 = (v00 > 0.0f) ? v00 + 1.0f : expf(v00);
                v01 = (v01 > 0.0f) ? v01 + 1.0f : expf(v01);
                v10 = (v10 > 0.0f) ? v10 + 1.0f : expf(v10);
                v11 = (v11 > 0.0f) ? v11 + 1.0f : expf(v11);
            }
            *(float2*)&C[(size_t)row * DMODEL + col]       = make_float2(v00, v01);
            *(float2*)&C[(size_t)(row + 8) * DMODEL + col] = make_float2(v10, v11);
        }
    }
}

// ---------------------------------------------------------------------------
// KV chain: kv[b,h,i,j] = sum_s V[b,s,h,i] * K[b,s,h,j];  ksum[b,h,j] = sum_s K
// ---------------------------------------------------------------------------
__global__ void __launch_bounds__(256)
kv_kernel(const float* __restrict__ K, const float* __restrict__ V,
          float* __restrict__ kv, float* __restrict__ ksum) {
    const int bh = blockIdx.x;
    const int b  = bh / NHEADS;
    const int h  = bh % NHEADS;
    const int tid = threadIdx.x;
    const int ty  = tid >> 4;
    const int tx  = tid & 15;

    __shared__ float Ks[16][64];
    __shared__ float Vs[16][64];

    float acc[4][4];
#pragma unroll
    for (int i = 0; i < 4; i++)
#pragma unroll
        for (int j = 0; j < 4; j++) acc[i][j] = 0.0f;
    float ks_acc = 0.0f;

    const float* Kbase = K + (size_t)b * S_LEN * DMODEL + h * DHEAD;
    const float* Vbase = V + (size_t)b * S_LEN * DMODEL + h * DHEAD;
    const int s0 = blockIdx.y * (S_LEN / 8);

    for (int s = s0; s < s0 + (S_LEN / 8); s += 16) {
        __syncthreads();
        {
            int r  = tid >> 4;
            int c4 = (tid & 15) << 2;
            *(float4*)&Ks[r][c4] = *(const float4*)&Kbase[(size_t)(s + r) * DMODEL + c4];
            *(float4*)&Vs[r][c4] = *(const float4*)&Vbase[(size_t)(s + r) * DMODEL + c4];
        }
        __syncthreads();
        if (tid < 64) {
#pragma unroll
            for (int ss = 0; ss < 16; ss++) ks_acc += Ks[ss][tid];
        }
#pragma unroll
        for (int ss = 0; ss < 16; ss++) {
            float vr[4], kr[4];
#pragma unroll
            for (int i = 0; i < 4; i++) vr[i] = Vs[ss][ty * 4 + i];
#pragma unroll
            for (int j = 0; j < 4; j++) kr[j] = Ks[ss][tx * 4 + j];
#pragma unroll
            for (int i = 0; i < 4; i++)
#pragma unroll
                for (int j = 0; j < 4; j++) acc[i][j] += vr[i] * kr[j];
        }
    }

    float* kvbh = kv + (size_t)bh * DHEAD * DHEAD;
#pragma unroll
    for (int i = 0; i < 4; i++)
#pragma unroll
        for (int j = 0; j < 4; j++)
            atomicAdd(&kvbh[(ty * 4 + i) * DHEAD + tx * 4 + j], acc[i][j]);
    if (tid < 64) atomicAdd(&ksum[bh * DHEAD + tid], ks_acc);
}

// ---------------------------------------------------------------------------
// Attention apply; output rounded to fp16 for the final GEMM
// ---------------------------------------------------------------------------
__global__ void __launch_bounds__(128)
attn_kernel(const float* __restrict__ Q, const float* __restrict__ kv,
            const float* __restrict__ ksum, __half* __restrict__ attn) {
    const int h   = blockIdx.y;
    const int row = blockIdx.x * 128 + threadIdx.x;
    const int b   = row / S_LEN;

    __shared__ float kvs[64][64];
    __shared__ float kss[64];

    const float* kvsrc = kv + (size_t)(b * NHEADS + h) * DHEAD * DHEAD;
    for (int i = threadIdx.x; i < (DHEAD * DHEAD) / 4; i += 128)
        ((float4*)kvs)[i] = ((const float4*)kvsrc)[i];
    if (threadIdx.x < 64) kss[threadIdx.x] = ksum[(b * NHEADS + h) * DHEAD + threadIdx.x];
    __syncthreads();

    float q[64];
    const float* qp = Q + (size_t)row * DMODEL + h * DHEAD;
#pragma unroll
    for (int i = 0; i < 16; i++) ((float4*)q)[i] = ((const float4*)qp)[i];

    float nd = 0.0f;
#pragma unroll
    for (int d = 0; d < 64; d++) nd += q[d] * kss[d];
    const float norm = 1.0f / (nd + 1e-6f);

    __half* op = attn + (size_t)row * DMODEL + h * DHEAD;
    for (int i0 = 0; i0 < 64; i0 += 4) {
        float out[4];
#pragma unroll
        for (int u = 0; u < 4; u++) {
            float s = 0.0f;
            const float4* kv4 = (const float4*)kvs[i0 + u];
#pragma unroll
            for (int d4 = 0; d4 < 16; d4++) {
                float4 kvv = kv4[d4];
                s += q[4*d4] * kvv.x + q[4*d4+1] * kvv.y
                   + q[4*d4+2] * kvv.z + q[4*d4+3] * kvv.w;
            }
            out[u] = s * norm;
        }
        __half2 h01 = __floats2half2_rn(out[0], out[1]);
        __half2 h23 = __floats2half2_rn(out[2], out[3]);
        *(__half2*)&op[i0]     = h01;
        *(__half2*)&op[i0 + 2] = h23;
    }
}

// ---------------------------------------------------------------------------
// Launch
// ---------------------------------------------------------------------------
extern "C" void kernel_launch(void* const* d_in, const int* in_sizes, int n_in,
                              void* d_out, int out_size) {
    const float* query = (const float*)d_in[0];
    const float* key_  = (const float*)d_in[1];
    const float* value = (const float*)d_in[2];
    const float* Wq = (const float*)d_in[3];
    const float* bq = (const float*)d_in[4];
    const float* Wk = (const float*)d_in[5];
    const float* bk = (const float*)d_in[6];
    const float* Wv = (const float*)d_in[7];
    const float* bv = (const float*)d_in[8];
    const float* Wo = (const float*)d_in[9];
    const float* bo = (const float*)d_in[10];
    float* out = (float*)d_out;

    float *qf, *kf, *vf, *kv, *ks;
    __half *hq, *hk, *hv, *hattn, *hw;
    cudaGetSymbolAddress((void**)&qf,    g_q);
    cudaGetSymbolAddress((void**)&kf,    g_k);
    cudaGetSymbolAddress((void**)&vf,    g_v);
    cudaGetSymbolAddress((void**)&kv,    g_kv);
    cudaGetSymbolAddress((void**)&ks,    g_ksum);
    cudaGetSymbolAddress((void**)&hq,    g_hq);
    cudaGetSymbolAddress((void**)&hk,    g_hk);
    cudaGetSymbolAddress((void**)&hv,    g_hv);
    cudaGetSymbolAddress((void**)&hattn, g_hattn);
    cudaGetSymbolAddress((void**)&hw,    g_hw);
    __half* hwq = hw;
    __half* hwk = hw + (size_t)DMODEL * DMODEL;
    __half* hwv = hw + (size_t)2 * DMODEL * DMODEL;
    __half* hwo = hw + (size_t)3 * DMODEL * DMODEL;

    static int smem_set = 0;
    if (!smem_set) {
        cudaFuncSetAttribute(gemm_fp16_kernel<1>,
                             cudaFuncAttributeMaxDynamicSharedMemorySize, GEMM_SMEM_BYTES);
        cudaFuncSetAttribute(gemm_fp16_kernel<0>,
                             cudaFuncAttributeMaxDynamicSharedMemorySize, GEMM_SMEM_BYTES);
        smem_set = 1;
    }

    // fp16 pre-rounding passes
    const int N4_IN = (NROWS * DMODEL) / 4;
    const int N4_W  = (DMODEL * DMODEL) / 4;
    round_fp16_kernel<<<N4_IN / 256, 256>>>(query, hq, N4_IN);
    round_fp16_kernel<<<N4_IN / 256, 256>>>(key_,  hk, N4_IN);
    round_fp16_kernel<<<N4_IN / 256, 256>>>(value, hv, N4_IN);
    round_fp16_kernel<<<N4_W / 256, 256>>>(Wq, hwq, N4_W);
    round_fp16_kernel<<<N4_W / 256, 256>>>(Wk, hwk, N4_W);
    round_fp16_kernel<<<N4_W / 256, 256>>>(Wv, hwv, N4_W);
    round_fp16_kernel<<<N4_W / 256, 256>>>(Wo, hwo, N4_W);

    // zero accumulators for atomics
    zero_kernel<<<(BATCH * NHEADS * DHEAD * DHEAD + 255) / 256, 256>>>(kv, BATCH * NHEADS * DHEAD * DHEAD);
    zero_kernel<<<(BATCH * NHEADS * DHEAD + 255) / 256, 256>>>(ks, BATCH * NHEADS * DHEAD);

    dim3 gemm_grid(DMODEL / BN, NROWS / BM);  // (8, 256)
    gemm_fp16_kernel<1><<<gemm_grid, 256, GEMM_SMEM_BYTES>>>(hq, hwq, bq, qf);
    gemm_fp16_kernel<1><<<gemm_grid, 256, GEMM_SMEM_BYTES>>>(hk, hwk, bk, kf);
    gemm_fp16_kernel<0><<<gemm_grid, 256, GEMM_SMEM_BYTES>>>(hv, hwv, bv, vf);

    kv_kernel<<<dim3(BATCH * NHEADS, 8), 256>>>(kf, vf, kv, ks);

    attn_kernel<<<dim3(NROWS / 128, NHEADS), 128>>>(qf, kv, ks, hattn);

    gemm_fp16_kernel<0><<<gemm_grid, 256, GEMM_SMEM_BYTES>>>(hattn, hwo, bo, out);
}